// round 3
// baseline (speedup 1.0000x reference)
#include <cuda_runtime.h>
#include <cuda_bf16.h>

#define NG 1024
#define HH 768
#define WW 768
#define TPX 8   // pixels per thread along w

// Per-gaussian coefficients, 12 floats each (3 x float4):
// [0]=mx [1]=-my [2]=A [3]=B [4]=D [5]=Dm(-2*D*my) [6]=Dm2(D*my*my)
// [7]=wr [8]=wg [9]=wb [10..11]=pad
__device__ __align__(16) float g_coef[NG * 12];

__global__ void prep_kernel(const float* __restrict__ means,
                            const float* __restrict__ cov,
                            const float* __restrict__ colors) {
    int n = blockIdx.x * blockDim.x + threadIdx.x;
    if (n >= NG) return;
    float mx = means[2 * n + 0];
    float my = means[2 * n + 1];
    float a = cov[4 * n + 0];
    float b = cov[4 * n + 1];
    float c = cov[4 * n + 2];
    float d = cov[4 * n + 3];
    float det = a * d - b * c;
    float ia  = d / det;
    float ibc = (-b - c) / det;   // ib + ic
    float idd = a / det;
    const float k = -0.72134752044448170368f;  // -0.5 * log2(e)
    float A = k * ia;
    float B = k * ibc;
    float D = k * idd;
    float Dm  = -2.0f * D * my;
    float Dm2 = D * my * my;
    float cr = colors[4 * n + 0];
    float cg = colors[4 * n + 1];
    float cb = colors[4 * n + 2];
    float al = colors[4 * n + 3];
    float wr = al / (1.0f + __expf(-cr));
    float wg = al / (1.0f + __expf(-cg));
    float wb = al / (1.0f + __expf(-cb));
    float* o = g_coef + 12 * n;
    o[0] = mx;  o[1] = -my; o[2]  = A;   o[3]  = B;
    o[4] = D;   o[5] = Dm;  o[6]  = Dm2; o[7]  = wr;
    o[8] = wg;  o[9] = wb;  o[10] = 0.f; o[11] = 0.f;
}

// Block tile: 128 pixels wide (16 segments of TPX=8) x 16 rows. Grid (6, 48).
__global__ __launch_bounds__(256)
void render_kernel(float* __restrict__ out) {
    __shared__ float4 sh[NG * 3];  // 48 KB
    {
        const float4* gc = (const float4*)g_coef;
        #pragma unroll 4
        for (int i = threadIdx.x; i < NG * 3; i += 256) sh[i] = gc[i];
    }
    __syncthreads();

    int tid = threadIdx.x;
    int seg = tid & 15;    // 0..15 -> which 8-pixel segment
    int row = tid >> 4;    // 0..15 -> row within tile
    int h  = blockIdx.y * 16 + row;
    int w0 = blockIdx.x * 128 + seg * TPX;

    const float inv = 1.0f / 767.0f;
    float x = (float)h * inv;

    float y[TPX], y2[TPX];
    #pragma unroll
    for (int j = 0; j < TPX; j++) {
        y[j]  = (float)(w0 + j) * inv;
        y2[j] = y[j] * y[j];
    }

    float ar[TPX], ag[TPX], ab[TPX];
    #pragma unroll
    for (int j = 0; j < TPX; j++) { ar[j] = 0.f; ag[j] = 0.f; ab[j] = 0.f; }

    #pragma unroll 2
    for (int n = 0; n < NG; n++) {
        float4 p0 = sh[3 * n + 0];
        float4 p1 = sh[3 * n + 1];
        float4 p2 = sh[3 * n + 2];
        float mx  = p0.x, nmy = p0.y, A = p0.z, B = p0.w;
        float D   = p1.x, Dm  = p1.y, Dm2 = p1.z, wr = p1.w;
        float wg  = p2.x, wb  = p2.y;

        // Hoist per (gaussian, row): arg(y) = e0 + e1*y + D*y^2
        float dx = x - mx;
        float t  = A * dx;
        float c1 = B * dx;
        float c0 = fmaf(t, dx, Dm2);
        float e1 = c1 + Dm;
        float e0 = fmaf(nmy, c1, c0);

        #pragma unroll
        for (int j = 0; j < TPX; j++) {
            float arg = fmaf(e1, y[j], fmaf(D, y2[j], e0));
            float v;
            asm("ex2.approx.ftz.f32 %0, %1;" : "=f"(v) : "f"(arg));
            ar[j] = fmaf(v, wr, ar[j]);
            ag[j] = fmaf(v, wg, ag[j]);
            ab[j] = fmaf(v, wb, ab[j]);
        }
    }

    #pragma unroll
    for (int j = 0; j < TPX; j++) {
        float* o = out + ((size_t)h * WW + (w0 + j)) * 3;
        o[0] = ar[j];
        o[1] = ag[j];
        o[2] = ab[j];
    }
}

extern "C" void kernel_launch(void* const* d_in, const int* in_sizes, int n_in,
                              void* d_out, int out_size) {
    const float* means  = (const float*)d_in[0];
    const float* cov    = (const float*)d_in[1];
    const float* colors = (const float*)d_in[2];
    float* out = (float*)d_out;

    prep_kernel<<<4, 256>>>(means, cov, colors);
    dim3 grid(WW / 128, HH / 16);
    render_kernel<<<grid, 256>>>(out);
}

// round 5
// speedup vs baseline: 1.1235x; 1.1235x over previous
#include <cuda_runtime.h>
#include <cuda_bf16.h>

#define NG 1024
#define HH 768
#define WW 768
#define TPX 8   // pixels per thread along w (4 f32x2 pairs)

// Per-gaussian coefficients, 12 floats (3 x float4):
// [0]=mx [1]=-my [2]=A [3]=B | [4]=D [5]=D(dup) [6]=Dm [7]=Dm2 | [8]=wr [9]=wg [10]=wb [11]=pad
__device__ __align__(16) float g_coef[NG * 12];

typedef unsigned long long u64;

__device__ __forceinline__ u64 pk2(float lo, float hi) {
    u64 d; asm("mov.b64 %0, {%1, %2};" : "=l"(d) : "f"(lo), "f"(hi)); return d;
}
__device__ __forceinline__ void upk2(u64 v, float& lo, float& hi) {
    asm("mov.b64 {%0, %1}, %2;" : "=f"(lo), "=f"(hi) : "l"(v));
}
__device__ __forceinline__ u64 fma2(u64 a, u64 b, u64 c) {
    u64 d; asm("fma.rn.f32x2 %0, %1, %2, %3;" : "=l"(d) : "l"(a), "l"(b), "l"(c)); return d;
}
__device__ __forceinline__ float ex2f(float a) {
    float v; asm("ex2.approx.ftz.f32 %0, %1;" : "=f"(v) : "f"(a)); return v;
}

__global__ void prep_kernel(const float* __restrict__ means,
                            const float* __restrict__ cov,
                            const float* __restrict__ colors) {
    int n = blockIdx.x * blockDim.x + threadIdx.x;
    if (n >= NG) return;
    float mx = means[2 * n + 0];
    float my = means[2 * n + 1];
    float a = cov[4 * n + 0];
    float b = cov[4 * n + 1];
    float c = cov[4 * n + 2];
    float d = cov[4 * n + 3];
    float det = a * d - b * c;
    float ia  = d / det;
    float ibc = (-b - c) / det;   // ib + ic
    float idd = a / det;
    const float k = -0.72134752044448170368f;  // -0.5 * log2(e)
    float A = k * ia;
    float B = k * ibc;
    float D = k * idd;
    float Dm  = -2.0f * D * my;
    float Dm2 = D * my * my;
    float cr = colors[4 * n + 0];
    float cg = colors[4 * n + 1];
    float cb = colors[4 * n + 2];
    float al = colors[4 * n + 3];
    float wr = al / (1.0f + __expf(-cr));
    float wg = al / (1.0f + __expf(-cg));
    float wb = al / (1.0f + __expf(-cb));
    float* o = g_coef + 12 * n;
    o[0] = mx; o[1] = -my; o[2] = A;  o[3] = B;
    o[4] = D;  o[5] = D;   o[6] = Dm; o[7] = Dm2;
    o[8] = wr; o[9] = wg;  o[10] = wb; o[11] = 0.f;
}

// Block tile: 128 pixels wide (16 segments of TPX=8) x 16 rows. Grid (6, 48).
__global__ __launch_bounds__(256)
void render_kernel(float* __restrict__ out) {
    __shared__ float4 sh[NG * 3];  // 48 KB
    {
        const float4* gc = (const float4*)g_coef;
        #pragma unroll 4
        for (int i = threadIdx.x; i < NG * 3; i += 256) sh[i] = gc[i];
    }
    __syncthreads();

    int tid = threadIdx.x;
    int seg = tid & 15;
    int row = tid >> 4;
    int h  = blockIdx.y * 16 + row;
    int w0 = blockIdx.x * 128 + seg * TPX;

    const float inv = 1.0f / 767.0f;
    float x = (float)h * inv;

    // Packed y and y^2 per pixel pair
    u64 yp[TPX / 2], y2p[TPX / 2];
    #pragma unroll
    for (int k = 0; k < TPX / 2; k++) {
        float ya = (float)(w0 + 2 * k)     * inv;
        float yb = (float)(w0 + 2 * k + 1) * inv;
        yp[k]  = pk2(ya, yb);
        y2p[k] = pk2(ya * ya, yb * yb);
    }

    u64 ar2[TPX / 2], ag2[TPX / 2], ab2[TPX / 2];
    #pragma unroll
    for (int k = 0; k < TPX / 2; k++) { ar2[k] = 0ull; ag2[k] = 0ull; ab2[k] = 0ull; }

    #pragma unroll 2
    for (int n = 0; n < NG; n++) {
        float4 p0 = sh[3 * n + 0];
        float4 p1 = sh[3 * n + 1];
        float4 p2 = sh[3 * n + 2];
        float mx  = p0.x, nmy = p0.y, A = p0.z, B = p0.w;
        float Dm  = p1.z, Dm2 = p1.w;
        u64 D2  = pk2(p1.x, p1.y);         // {D, D} (pre-duplicated in smem)
        u64 wr2 = pk2(p2.x, p2.x);
        u64 wg2 = pk2(p2.y, p2.y);
        u64 wb2 = pk2(p2.z, p2.z);

        // Hoist per (gaussian, row): arg(y) = e0 + e1*y + D*y^2
        float dx = x - mx;
        float t  = A * dx;
        float c1 = B * dx;
        float c0 = fmaf(t, dx, Dm2);
        float e1 = c1 + Dm;
        float e0 = fmaf(nmy, c1, c0);
        u64 e0_2 = pk2(e0, e0);
        u64 e1_2 = pk2(e1, e1);

        #pragma unroll
        for (int k = 0; k < TPX / 2; k++) {
            u64 t2   = fma2(D2, y2p[k], e0_2);
            u64 arg2 = fma2(e1_2, yp[k], t2);
            float a0, a1;
            upk2(arg2, a0, a1);
            float v0 = ex2f(a0);
            float v1 = ex2f(a1);
            u64 v2 = pk2(v0, v1);
            ar2[k] = fma2(v2, wr2, ar2[k]);
            ag2[k] = fma2(v2, wg2, ag2[k]);
            ab2[k] = fma2(v2, wb2, ab2[k]);
        }
    }

    // Unpack and store: 24 contiguous floats per thread -> 6 x STG.128
    float r[TPX], g[TPX], b[TPX];
    #pragma unroll
    for (int k = 0; k < TPX / 2; k++) {
        upk2(ar2[k], r[2 * k], r[2 * k + 1]);
        upk2(ag2[k], g[2 * k], g[2 * k + 1]);
        upk2(ab2[k], b[2 * k], b[2 * k + 1]);
    }
    float buf[24];
    #pragma unroll
    for (int j = 0; j < TPX; j++) {
        buf[3 * j + 0] = r[j];
        buf[3 * j + 1] = g[j];
        buf[3 * j + 2] = b[j];
    }
    float4* o = (float4*)(out + ((size_t)h * WW + w0) * 3);
    #pragma unroll
    for (int q = 0; q < 6; q++) o[q] = ((float4*)buf)[q];
}

extern "C" void kernel_launch(void* const* d_in, const int* in_sizes, int n_in,
                              void* d_out, int out_size) {
    const float* means  = (const float*)d_in[0];
    const float* cov    = (const float*)d_in[1];
    const float* colors = (const float*)d_in[2];
    float* out = (float*)d_out;

    prep_kernel<<<4, 256>>>(means, cov, colors);
    dim3 grid(WW / 128, HH / 16);
    render_kernel<<<grid, 256>>>(out);
}

// round 6
// speedup vs baseline: 1.3095x; 1.1656x over previous
#include <cuda_runtime.h>
#include <cuda_bf16.h>

#define NG 1024
#define HH 768
#define WW 768
#define TPX 16   // pixels per thread along w (8 f32x2 pairs)

// Per-gaussian coefficients, 12 floats (3 x float4):
// [0]=mx [1]=-my [2]=A [3]=B | [4]=D [5]=Dm [6]=Dm2 [7]=s | [8]=wr [9]=wg [10]=wb [11]=pad
// A,B,D already scaled by -0.5*log2(e); s = 2^(2*D*delta^2)
__device__ __align__(16) float g_coef[NG * 12];

typedef unsigned long long u64;

__device__ __forceinline__ u64 pk2(float lo, float hi) {
    u64 d; asm("mov.b64 %0, {%1, %2};" : "=l"(d) : "f"(lo), "f"(hi)); return d;
}
__device__ __forceinline__ void upk2(u64 v, float& lo, float& hi) {
    asm("mov.b64 {%0, %1}, %2;" : "=f"(lo), "=f"(hi) : "l"(v));
}
__device__ __forceinline__ u64 fma2(u64 a, u64 b, u64 c) {
    u64 d; asm("fma.rn.f32x2 %0, %1, %2, %3;" : "=l"(d) : "l"(a), "l"(b), "l"(c)); return d;
}
__device__ __forceinline__ u64 mul2(u64 a, u64 b) {
    u64 d; asm("mul.rn.f32x2 %0, %1, %2;" : "=l"(d) : "l"(a), "l"(b)); return d;
}
__device__ __forceinline__ float ex2f(float a) {
    float v; asm("ex2.approx.ftz.f32 %0, %1;" : "=f"(v) : "f"(a)); return v;
}

__global__ void prep_kernel(const float* __restrict__ means,
                            const float* __restrict__ cov,
                            const float* __restrict__ colors) {
    int n = blockIdx.x * blockDim.x + threadIdx.x;
    if (n >= NG) return;
    float mx = means[2 * n + 0];
    float my = means[2 * n + 1];
    float a = cov[4 * n + 0];
    float b = cov[4 * n + 1];
    float c = cov[4 * n + 2];
    float d = cov[4 * n + 3];
    float det = a * d - b * c;
    float ia  = d / det;
    float ibc = (-b - c) / det;   // ib + ic
    float idd = a / det;
    const float k = -0.72134752044448170368f;  // -0.5 * log2(e)
    float A = k * ia;
    float B = k * ibc;
    float D = k * idd;
    float Dm  = -2.0f * D * my;
    float Dm2 = D * my * my;
    const float delta = 1.0f / 767.0f;
    float s = exp2f(2.0f * D * delta * delta);   // per-gaussian recurrence ratio-of-ratios
    float cr = colors[4 * n + 0];
    float cg = colors[4 * n + 1];
    float cb = colors[4 * n + 2];
    float al = colors[4 * n + 3];
    float wr = al / (1.0f + __expf(-cr));
    float wg = al / (1.0f + __expf(-cg));
    float wb = al / (1.0f + __expf(-cb));
    float* o = g_coef + 12 * n;
    o[0] = mx; o[1] = -my; o[2] = A;   o[3] = B;
    o[4] = D;  o[5] = Dm;  o[6] = Dm2; o[7] = s;
    o[8] = wr; o[9] = wg;  o[10] = wb; o[11] = 0.f;
}

// Block: 128 threads = 8 segments (16 px each, 128 px wide) x 16 rows.
// Grid (768/128, 768/16) = (6, 48) = 288 blocks.
__global__ __launch_bounds__(128)
void render_kernel(float* __restrict__ out) {
    __shared__ float4 sh[NG * 3];  // 48 KB
    {
        const float4* gc = (const float4*)g_coef;
        #pragma unroll 8
        for (int i = threadIdx.x; i < NG * 3; i += 128) sh[i] = gc[i];
    }
    __syncthreads();

    int tid = threadIdx.x;
    int seg = tid & 7;     // 0..7 -> which 16-pixel segment
    int row = tid >> 3;    // 0..15 -> row within tile
    int h  = blockIdx.y * 16 + row;
    int w0 = blockIdx.x * 128 + seg * TPX;

    const float inv = 1.0f / 767.0f;   // delta
    float x  = (float)h * inv;
    float y0 = (float)w0 * inv;
    float y0sq   = y0 * y0;
    float c2y0d  = 2.0f * y0 + inv;    // (2*y0 + delta), for r0 arg

    u64 ar2[TPX / 2], ag2[TPX / 2], ab2[TPX / 2];
    #pragma unroll
    for (int kk = 0; kk < TPX / 2; kk++) { ar2[kk] = 0ull; ag2[kk] = 0ull; ab2[kk] = 0ull; }

    #pragma unroll 2
    for (int n = 0; n < NG; n++) {
        float4 p0 = sh[3 * n + 0];
        float4 p1 = sh[3 * n + 1];
        float4 p2 = sh[3 * n + 2];
        float mx  = p0.x, nmy = p0.y, A = p0.z, B = p0.w;
        float D   = p1.x, Dm  = p1.y, Dm2 = p1.z, s = p1.w;
        u64 wr2 = pk2(p2.x, p2.x);
        u64 wg2 = pk2(p2.y, p2.y);
        u64 wb2 = pk2(p2.z, p2.z);

        // Hoist per (gaussian, row): arg(y) = e0 + e1*y + D*y^2
        float dx = x - mx;
        float t  = A * dx;
        float c1 = B * dx;
        float c0 = fmaf(t, dx, Dm2);
        float e1 = c1 + Dm;
        float e0 = fmaf(nmy, c1, c0);

        // v0 = 2^(arg at y0); r0 = v1/v0 = 2^(delta*(e1 + D*(2*y0+delta)))
        float arg0  = fmaf(e1, y0, fmaf(D, y0sq, e0));
        float rarg  = inv * fmaf(D, c2y0d, e1);
        float v0 = ex2f(arg0);
        float r0 = ex2f(rarg);

        // s powers (3 muls, amortized over 16 px)
        float s2 = s * s;
        float s3 = s2 * s;
        float s4 = s2 * s2;

        float v1  = v0 * r0;
        float r0q = r0 * r0;
        u64 V  = pk2(v0, v1);
        u64 P  = mul2(pk2(r0q, r0q), pk2(s, s3));   // {r0^2*s, r0^2*s^3}
        u64 S4 = pk2(s4, s4);

        #pragma unroll
        for (int kk = 0; kk < TPX / 2; kk++) {
            ar2[kk] = fma2(V, wr2, ar2[kk]);
            ag2[kk] = fma2(V, wg2, ag2[kk]);
            ab2[kk] = fma2(V, wb2, ab2[kk]);
            if (kk < TPX / 2 - 1) {
                V = mul2(V, P);
                if (kk < TPX / 2 - 2) P = mul2(P, S4);
            }
        }
    }

    // Unpack and store: 48 contiguous floats per thread -> 12 x STG.128
    float r[TPX], g[TPX], b[TPX];
    #pragma unroll
    for (int kk = 0; kk < TPX / 2; kk++) {
        upk2(ar2[kk], r[2 * kk], r[2 * kk + 1]);
        upk2(ag2[kk], g[2 * kk], g[2 * kk + 1]);
        upk2(ab2[kk], b[2 * kk], b[2 * kk + 1]);
    }
    float buf[TPX * 3];
    #pragma unroll
    for (int j = 0; j < TPX; j++) {
        buf[3 * j + 0] = r[j];
        buf[3 * j + 1] = g[j];
        buf[3 * j + 2] = b[j];
    }
    float4* o = (float4*)(out + ((size_t)h * WW + w0) * 3);
    #pragma unroll
    for (int q = 0; q < TPX * 3 / 4; q++) o[q] = ((float4*)buf)[q];
}

extern "C" void kernel_launch(void* const* d_in, const int* in_sizes, int n_in,
                              void* d_out, int out_size) {
    const float* means  = (const float*)d_in[0];
    const float* cov    = (const float*)d_in[1];
    const float* colors = (const float*)d_in[2];
    float* out = (float*)d_out;

    prep_kernel<<<4, 256>>>(means, cov, colors);
    dim3 grid(WW / (8 * TPX), HH / 16);
    render_kernel<<<grid, 128>>>(out);
}